// round 16
// baseline (speedup 1.0000x reference)
#include <cuda_runtime.h>
#include <cuda_fp16.h>
#include <cstdint>

#define N_NODES 100000
#define N_EDGES 1600000
#define D_IN    128
#define D_OUT   64

// Scratch: h = x @ W in fp16 (100000 x 64 halves = 12.8 MB, L2-resident).
__device__ __align__(256) uint32_t g_h16[N_NODES * 32];

// CSR build state
__device__ int  g_cnt[N_NODES + 1];          // counts, then cursors
__device__ int  g_off[N_NODES + 1];          // exclusive offsets
__device__ int  g_bsum[128];                 // scan block sums (98 used)
__device__ __align__(16) int2 g_pairs[N_EDGES];  // (dst, w-bits) grouped by src

// Index-width flag: 1 = indices are int64, 0 = int32
__device__ int g_idx64;

__device__ __forceinline__ uint32_t f2h2(float a, float b) {
    const __half2 h = __floats2half2_rn(a, b);
    return *(const uint32_t*)&h;
}
__device__ __forceinline__ int load_idx(const int* p, int e, int idx64) {
    return idx64 ? __ldg(p + 2 * e) : __ldg(p + e);   // LE low word of int64
}

// ---------------------------------------------------------------------------
// Kernel A: zero counts + index-width probe (block 0)
// ---------------------------------------------------------------------------
__global__ void __launch_bounds__(256) zero_probe_kernel(const void* __restrict__ src) {
    if (blockIdx.x == 0 && threadIdx.x == 0) {
        // int32 data read as u64 packs two indices -> top bits nonzero w.h.p.
        const unsigned long long* p = (const unsigned long long*)src;
        int is64 = 1;
        for (int i = 0; i < 8; i++)
            if (p[i] >= (unsigned long long)N_NODES) is64 = 0;
        g_idx64 = is64;
    }
    const int i = blockIdx.x * 256 + threadIdx.x;
    if (i <= N_NODES) g_cnt[i] = 0;
}

// ---------------------------------------------------------------------------
// Kernel B: h = x @ W.  R12 GEMM shape with minimum 4 CTAs/SM (caps regs at
// 128 -> 16 warps/SM vs 12): 128 threads, 8x8 tile, k by 32, f32x2 FMA.
// ---------------------------------------------------------------------------
__global__ void __launch_bounds__(128, 4) gemm_kernel(const float* __restrict__ x,
                                                      const float* __restrict__ W) {
    __shared__ float Ws[D_IN * D_OUT];   // 32 KB, [k][col]
    __shared__ float Xs[128 * 32];       // 16 KB, [row][k-local]

    const int tid = threadIdx.x;

    {
        const float4* Wg  = (const float4*)W;
        float4*       Wsv = (float4*)Ws;
#pragma unroll
        for (int i = 0; i < 16; i++) Wsv[tid + i * 128] = Wg[tid + i * 128];
    }

    const int row0 = blockIdx.x * 128;
    const int tx = tid & 7;
    const int ty = tid >> 3;

    unsigned long long acc[8][4];
#pragma unroll
    for (int r = 0; r < 8; r++)
#pragma unroll
        for (int c = 0; c < 4; c++) acc[r][c] = 0ull;

    for (int k0 = 0; k0 < D_IN; k0 += 32) {
        __syncthreads();
#pragma unroll
        for (int i = 0; i < 8; i++) {
            const int lin  = tid + i * 128;
            const int row  = lin >> 3;
            const int slot = lin & 7;
            int grow = row0 + row;
            if (grow >= N_NODES) grow = N_NODES - 1;
            const float4 v =
                __ldg((const float4*)(x + (size_t)grow * D_IN + k0) + slot);
            *(float4*)&Xs[row * 32 + slot * 4] = v;
        }
        __syncthreads();

#pragma unroll
        for (int kk = 0; kk < 32; kk += 4) {
            float4 xv[8];
#pragma unroll
            for (int r = 0; r < 8; r++)
                xv[r] = *(const float4*)&Xs[(ty * 8 + r) * 32 + kk];
#pragma unroll
            for (int j = 0; j < 4; j++) {
                const ulonglong2 wvA =
                    *(const ulonglong2*)&Ws[(k0 + kk + j) * D_OUT + 8 * tx];
                const ulonglong2 wvB =
                    *(const ulonglong2*)&Ws[(k0 + kk + j) * D_OUT + 8 * tx + 4];
#pragma unroll
                for (int r = 0; r < 8; r++) {
                    const float xs = (j == 0) ? xv[r].x : (j == 1) ? xv[r].y
                                   : (j == 2) ? xv[r].z : xv[r].w;
                    unsigned long long d;
                    asm("mov.b64 %0, {%1, %1};" : "=l"(d) : "f"(xs));
                    asm("fma.rn.f32x2 %0, %1, %2, %0;" : "+l"(acc[r][0]) : "l"(d), "l"(wvA.x));
                    asm("fma.rn.f32x2 %0, %1, %2, %0;" : "+l"(acc[r][1]) : "l"(d), "l"(wvA.y));
                    asm("fma.rn.f32x2 %0, %1, %2, %0;" : "+l"(acc[r][2]) : "l"(d), "l"(wvB.x));
                    asm("fma.rn.f32x2 %0, %1, %2, %0;" : "+l"(acc[r][3]) : "l"(d), "l"(wvB.y));
                }
            }
        }
    }

#pragma unroll
    for (int r = 0; r < 8; r++) {
        const int row = row0 + ty * 8 + r;
        if (row < N_NODES) {
            float4 lo, hi;
            asm("mov.b64 {%0, %1}, %2;" : "=f"(lo.x), "=f"(lo.y) : "l"(acc[r][0]));
            asm("mov.b64 {%0, %1}, %2;" : "=f"(lo.z), "=f"(lo.w) : "l"(acc[r][1]));
            asm("mov.b64 {%0, %1}, %2;" : "=f"(hi.x), "=f"(hi.y) : "l"(acc[r][2]));
            asm("mov.b64 {%0, %1}, %2;" : "=f"(hi.z), "=f"(hi.w) : "l"(acc[r][3]));
            uint4 pk;
            pk.x = f2h2(lo.x, lo.y);
            pk.y = f2h2(lo.z, lo.w);
            pk.z = f2h2(hi.x, hi.y);
            pk.w = f2h2(hi.z, hi.w);
            *(uint4*)&g_h16[(size_t)row * 32 + 4 * tx] = pk;
        }
    }
}

// ---------------------------------------------------------------------------
// Kernel C: histogram of src
// ---------------------------------------------------------------------------
__global__ void __launch_bounds__(256) hist_kernel(const void* __restrict__ srcp) {
    const int e = blockIdx.x * 256 + threadIdx.x;   // 1.6M exact
    const int s = load_idx((const int*)srcp, e, g_idx64);
    if ((unsigned)s < N_NODES) atomicAdd(&g_cnt[s], 1);
}

// ---------------------------------------------------------------------------
// Kernel D1: per-1024-chunk exclusive scan of counts -> g_off partials + bsum
// ---------------------------------------------------------------------------
__global__ void __launch_bounds__(256) scan1_kernel() {
    __shared__ int ss[256];
    const int tid  = threadIdx.x;
    const int base = blockIdx.x * 1024 + tid * 4;

    int v[4], t = 0;
#pragma unroll
    for (int q = 0; q < 4; q++) {
        const int idx = base + q;
        v[q] = (idx < N_NODES) ? g_cnt[idx] : 0;
        t += v[q];
    }
    ss[tid] = t;
    __syncthreads();
    for (int o = 1; o < 256; o <<= 1) {
        const int u = (tid >= o) ? ss[tid - o] : 0;
        __syncthreads();
        ss[tid] += u;
        __syncthreads();
    }
    int acc = ss[tid] - t;   // exclusive within chunk
#pragma unroll
    for (int q = 0; q < 4; q++) {
        const int idx = base + q;
        if (idx < N_NODES) g_off[idx] = acc;
        acc += v[q];
    }
    if (tid == 255) g_bsum[blockIdx.x] = ss[255];
}

// ---------------------------------------------------------------------------
// Kernel D2: exclusive scan of the 98 block sums (in place)
// ---------------------------------------------------------------------------
__global__ void __launch_bounds__(128) scan2_kernel() {
    __shared__ int sb[128];
    const int tid = threadIdx.x;
    const int v = (tid < 98) ? g_bsum[tid] : 0;
    sb[tid] = v;
    __syncthreads();
    for (int o = 1; o < 128; o <<= 1) {
        const int u = (tid >= o) ? sb[tid - o] : 0;
        __syncthreads();
        sb[tid] += u;
        __syncthreads();
    }
    g_bsum[tid] = sb[tid] - v;   // exclusive
}

// ---------------------------------------------------------------------------
// Kernel D3: finalize offsets, copy to cursors
// ---------------------------------------------------------------------------
__global__ void __launch_bounds__(256) scan3_kernel() {
    const int i = blockIdx.x * 256 + threadIdx.x;
    if (i < N_NODES) {
        const int f = g_off[i] + g_bsum[i >> 10];
        g_off[i] = f;
        g_cnt[i] = f;           // cursor
    } else if (i == N_NODES) {
        g_off[N_NODES] = N_EDGES;
    }
}

// ---------------------------------------------------------------------------
// Kernel E: permute edges into src-grouped order as (dst, w-bits) pairs
// ---------------------------------------------------------------------------
__global__ void __launch_bounds__(256) perm_kernel(
    const float* __restrict__ ew,
    const void* __restrict__ srcp,
    const void* __restrict__ dstp) {
    const int e = blockIdx.x * 256 + threadIdx.x;   // 1.6M exact
    const int idx64 = g_idx64;
    const int s = load_idx((const int*)srcp, e, idx64);
    const int d = load_idx((const int*)dstp, e, idx64);
    const float w = __ldg(ew + e);
    if ((unsigned)s < N_NODES) {
        const int pos = atomicAdd(&g_cnt[s], 1);
        g_pairs[pos] = make_int2(d, __float_as_int(w));
    }
}

// ---------------------------------------------------------------------------
// Kernel F: per-node aggregation + ReLU.  Half-warp (16 lanes) per node:
// lane hl covers cols [4hl, 4hl+3].  4-edge inner unroll: 4 independent
// pair-loads then 4 independent gathers in flight per iteration.
// ---------------------------------------------------------------------------
__global__ void __launch_bounds__(256) agg_kernel(float* __restrict__ out) {
    const int warp = threadIdx.x >> 5;
    const int lane = threadIdx.x & 31;
    const int half = lane >> 4;
    const int hl   = lane & 15;
    const int node = blockIdx.x * 16 + warp * 2 + half;   // 6250*16 = 100000

    const int b  = __ldg(&g_off[node]);
    const int e2 = __ldg(&g_off[node + 1]);

    float4 acc = make_float4(0.f, 0.f, 0.f, 0.f);

    int j = b;
    for (; j + 3 < e2; j += 4) {
        int2 c0 = __ldg(&g_pairs[j]);
        int2 c1 = __ldg(&g_pairs[j + 1]);
        int2 c2 = __ldg(&g_pairs[j + 2]);
        int2 c3 = __ldg(&g_pairs[j + 3]);
        const uint2 h0 = __ldg((const uint2*)(g_h16 + (size_t)c0.x * 32) + hl);
        const uint2 h1 = __ldg((const uint2*)(g_h16 + (size_t)c1.x * 32) + hl);
        const uint2 h2 = __ldg((const uint2*)(g_h16 + (size_t)c2.x * 32) + hl);
        const uint2 h3 = __ldg((const uint2*)(g_h16 + (size_t)c3.x * 32) + hl);
#pragma unroll
        for (int q = 0; q < 4; q++) {
            const uint2 hv = (q == 0) ? h0 : (q == 1) ? h1 : (q == 2) ? h2 : h3;
            const float wv = __int_as_float((q == 0) ? c0.y : (q == 1) ? c1.y
                                           : (q == 2) ? c2.y : c3.y);
            const float2 f0 = __half22float2(*(const __half2*)&hv.x);
            const float2 f1 = __half22float2(*(const __half2*)&hv.y);
            acc.x += wv * f0.x;
            acc.y += wv * f0.y;
            acc.z += wv * f1.x;
            acc.w += wv * f1.y;
        }
    }
    for (; j < e2; j++) {
        const int2 cur = __ldg(&g_pairs[j]);
        const uint2 hv = __ldg((const uint2*)(g_h16 + (size_t)cur.x * 32) + hl);
        const float wv = __int_as_float(cur.y);
        const float2 f0 = __half22float2(*(const __half2*)&hv.x);
        const float2 f1 = __half22float2(*(const __half2*)&hv.y);
        acc.x += wv * f0.x;
        acc.y += wv * f0.y;
        acc.z += wv * f1.x;
        acc.w += wv * f1.y;
    }

    float4 r;
    r.x = fmaxf(acc.x, 0.f);
    r.y = fmaxf(acc.y, 0.f);
    r.z = fmaxf(acc.z, 0.f);
    r.w = fmaxf(acc.w, 0.f);
    *(float4*)(out + (size_t)node * D_OUT + 4 * hl) = r;
}

// ---------------------------------------------------------------------------
extern "C" void kernel_launch(void* const* d_in, const int* in_sizes, int n_in,
                              void* d_out, int out_size) {
    const float* x   = (const float*)d_in[0];      // [100000, 128]
    const float* ew  = (const float*)d_in[1];      // [1600000]
    const float* W   = (const float*)d_in[2];      // [128, 64]
    const void*  src = d_in[3];                    // [1600000] int64/int32
    const void*  dst = d_in[4];                    // [1600000] int64/int32
    float* out = (float*)d_out;                    // [100000, 64]

    // Lazily-created side stream + fork/join events (host objects).
    static cudaStream_t s2 = nullptr;
    static cudaEvent_t ev_fork = nullptr, ev_join = nullptr;
    if (s2 == nullptr) {
        cudaStreamCreateWithFlags(&s2, cudaStreamNonBlocking);
        cudaEventCreateWithFlags(&ev_fork, cudaEventDisableTiming);
        cudaEventCreateWithFlags(&ev_join, cudaEventDisableTiming);
    }

    // ---- fork: CSR build runs on s2, concurrent with the GEMM.
    cudaEventRecord(ev_fork, 0);
    cudaStreamWaitEvent(s2, ev_fork, 0);

    // branch A (main stream): h = x @ W
    gemm_kernel<<<(N_NODES + 127) / 128, 128>>>(x, W);

    // branch B (s2): CSR build
    zero_probe_kernel<<<392, 256, 0, s2>>>(src);
    hist_kernel<<<N_EDGES / 256, 256, 0, s2>>>(src);
    scan1_kernel<<<98, 256, 0, s2>>>();
    scan2_kernel<<<1, 128, 0, s2>>>();
    scan3_kernel<<<392, 256, 0, s2>>>();
    perm_kernel<<<N_EDGES / 256, 256, 0, s2>>>(ew, src, dst);

    // ---- join, then aggregate (+ReLU) on the main stream
    cudaEventRecord(ev_join, s2);
    cudaStreamWaitEvent(0, ev_join, 0);
    agg_kernel<<<N_NODES / 16, 256>>>(out);
}

// round 17
// speedup vs baseline: 1.4053x; 1.4053x over previous
#include <cuda_runtime.h>
#include <cuda_fp16.h>
#include <cstdint>

#define N_NODES 100000
#define N_EDGES 1600000
#define D_IN    128
#define D_OUT   64

// Scratch: h = x @ W in fp16 (100000 x 64 halves = 12.8 MB, L2-resident).
__device__ __align__(256) uint32_t g_h16[N_NODES * 32];

// CSR build state
__device__ int  g_cnt[N_NODES + 1];          // counts, then cursors
__device__ int  g_off[N_NODES + 1];          // exclusive offsets
__device__ int  g_bsum[128];                 // scan block sums (98 used)
__device__ __align__(16) int2 g_pairs[N_EDGES];  // (dst, w-bits) grouped by src

// Index-width flag: 1 = indices are int64, 0 = int32
__device__ int g_idx64;

__device__ __forceinline__ uint32_t f2h2(float a, float b) {
    const __half2 h = __floats2half2_rn(a, b);
    return *(const uint32_t*)&h;
}
__device__ __forceinline__ int load_idx(const int* p, int e, int idx64) {
    return idx64 ? __ldg(p + 2 * e) : __ldg(p + e);   // LE low word of int64
}

// ---------------------------------------------------------------------------
// Kernel A: zero counts + index-width probe (block 0)
// ---------------------------------------------------------------------------
__global__ void __launch_bounds__(256) zero_probe_kernel(const void* __restrict__ src) {
    if (blockIdx.x == 0 && threadIdx.x == 0) {
        // int32 data read as u64 packs two indices -> top bits nonzero w.h.p.
        const unsigned long long* p = (const unsigned long long*)src;
        int is64 = 1;
        for (int i = 0; i < 8; i++)
            if (p[i] >= (unsigned long long)N_NODES) is64 = 0;
        g_idx64 = is64;
    }
    const int i = blockIdx.x * 256 + threadIdx.x;
    if (i <= N_NODES) g_cnt[i] = 0;
}

// ---------------------------------------------------------------------------
// Kernel B: h = x @ W.  R15-exact GEMM (measured 48.7us): 128 threads,
// 8x8 thread tile, k by 32 through smem, f32x2 FMA, fp16 out.  NO min-blocks
// cap: regs 152 is real; capping to 128 spills the hot loop (R16 lesson).
// ---------------------------------------------------------------------------
__global__ void __launch_bounds__(128) gemm_kernel(const float* __restrict__ x,
                                                   const float* __restrict__ W) {
    __shared__ float Ws[D_IN * D_OUT];   // 32 KB, [k][col]
    __shared__ float Xs[128 * 32];       // 16 KB, [row][k-local]

    const int tid = threadIdx.x;

    {
        const float4* Wg  = (const float4*)W;
        float4*       Wsv = (float4*)Ws;
#pragma unroll
        for (int i = 0; i < 16; i++) Wsv[tid + i * 128] = Wg[tid + i * 128];
    }

    const int row0 = blockIdx.x * 128;
    const int tx = tid & 7;
    const int ty = tid >> 3;

    unsigned long long acc[8][4];
#pragma unroll
    for (int r = 0; r < 8; r++)
#pragma unroll
        for (int c = 0; c < 4; c++) acc[r][c] = 0ull;

    for (int k0 = 0; k0 < D_IN; k0 += 32) {
        __syncthreads();
#pragma unroll
        for (int i = 0; i < 8; i++) {
            const int lin  = tid + i * 128;
            const int row  = lin >> 3;
            const int slot = lin & 7;
            int grow = row0 + row;
            if (grow >= N_NODES) grow = N_NODES - 1;
            const float4 v =
                __ldg((const float4*)(x + (size_t)grow * D_IN + k0) + slot);
            *(float4*)&Xs[row * 32 + slot * 4] = v;
        }
        __syncthreads();

#pragma unroll
        for (int kk = 0; kk < 32; kk += 4) {
            float4 xv[8];
#pragma unroll
            for (int r = 0; r < 8; r++)
                xv[r] = *(const float4*)&Xs[(ty * 8 + r) * 32 + kk];
#pragma unroll
            for (int j = 0; j < 4; j++) {
                const ulonglong2 wvA =
                    *(const ulonglong2*)&Ws[(k0 + kk + j) * D_OUT + 8 * tx];
                const ulonglong2 wvB =
                    *(const ulonglong2*)&Ws[(k0 + kk + j) * D_OUT + 8 * tx + 4];
#pragma unroll
                for (int r = 0; r < 8; r++) {
                    const float xs = (j == 0) ? xv[r].x : (j == 1) ? xv[r].y
                                   : (j == 2) ? xv[r].z : xv[r].w;
                    unsigned long long d;
                    asm("mov.b64 %0, {%1, %1};" : "=l"(d) : "f"(xs));
                    asm("fma.rn.f32x2 %0, %1, %2, %0;" : "+l"(acc[r][0]) : "l"(d), "l"(wvA.x));
                    asm("fma.rn.f32x2 %0, %1, %2, %0;" : "+l"(acc[r][1]) : "l"(d), "l"(wvA.y));
                    asm("fma.rn.f32x2 %0, %1, %2, %0;" : "+l"(acc[r][2]) : "l"(d), "l"(wvB.x));
                    asm("fma.rn.f32x2 %0, %1, %2, %0;" : "+l"(acc[r][3]) : "l"(d), "l"(wvB.y));
                }
            }
        }
    }

#pragma unroll
    for (int r = 0; r < 8; r++) {
        const int row = row0 + ty * 8 + r;
        if (row < N_NODES) {
            float4 lo, hi;
            asm("mov.b64 {%0, %1}, %2;" : "=f"(lo.x), "=f"(lo.y) : "l"(acc[r][0]));
            asm("mov.b64 {%0, %1}, %2;" : "=f"(lo.z), "=f"(lo.w) : "l"(acc[r][1]));
            asm("mov.b64 {%0, %1}, %2;" : "=f"(hi.x), "=f"(hi.y) : "l"(acc[r][2]));
            asm("mov.b64 {%0, %1}, %2;" : "=f"(hi.z), "=f"(hi.w) : "l"(acc[r][3]));
            uint4 pk;
            pk.x = f2h2(lo.x, lo.y);
            pk.y = f2h2(lo.z, lo.w);
            pk.z = f2h2(hi.x, hi.y);
            pk.w = f2h2(hi.z, hi.w);
            *(uint4*)&g_h16[(size_t)row * 32 + 4 * tx] = pk;
        }
    }
}

// ---------------------------------------------------------------------------
// Kernel C: histogram of src
// ---------------------------------------------------------------------------
__global__ void __launch_bounds__(256) hist_kernel(const void* __restrict__ srcp) {
    const int e = blockIdx.x * 256 + threadIdx.x;   // 1.6M exact
    const int s = load_idx((const int*)srcp, e, g_idx64);
    if ((unsigned)s < N_NODES) atomicAdd(&g_cnt[s], 1);
}

// ---------------------------------------------------------------------------
// Kernel D1: per-1024-chunk exclusive scan of counts -> g_off partials + bsum
// ---------------------------------------------------------------------------
__global__ void __launch_bounds__(256) scan1_kernel() {
    __shared__ int ss[256];
    const int tid  = threadIdx.x;
    const int base = blockIdx.x * 1024 + tid * 4;

    int v[4], t = 0;
#pragma unroll
    for (int q = 0; q < 4; q++) {
        const int idx = base + q;
        v[q] = (idx < N_NODES) ? g_cnt[idx] : 0;
        t += v[q];
    }
    ss[tid] = t;
    __syncthreads();
    for (int o = 1; o < 256; o <<= 1) {
        const int u = (tid >= o) ? ss[tid - o] : 0;
        __syncthreads();
        ss[tid] += u;
        __syncthreads();
    }
    int acc = ss[tid] - t;   // exclusive within chunk
#pragma unroll
    for (int q = 0; q < 4; q++) {
        const int idx = base + q;
        if (idx < N_NODES) g_off[idx] = acc;
        acc += v[q];
    }
    if (tid == 255) g_bsum[blockIdx.x] = ss[255];
}

// ---------------------------------------------------------------------------
// Kernel D2: exclusive scan of the 98 block sums (in place)
// ---------------------------------------------------------------------------
__global__ void __launch_bounds__(128) scan2_kernel() {
    __shared__ int sb[128];
    const int tid = threadIdx.x;
    const int v = (tid < 98) ? g_bsum[tid] : 0;
    sb[tid] = v;
    __syncthreads();
    for (int o = 1; o < 128; o <<= 1) {
        const int u = (tid >= o) ? sb[tid - o] : 0;
        __syncthreads();
        sb[tid] += u;
        __syncthreads();
    }
    g_bsum[tid] = sb[tid] - v;   // exclusive
}

// ---------------------------------------------------------------------------
// Kernel D3: finalize offsets, copy to cursors
// ---------------------------------------------------------------------------
__global__ void __launch_bounds__(256) scan3_kernel() {
    const int i = blockIdx.x * 256 + threadIdx.x;
    if (i < N_NODES) {
        const int f = g_off[i] + g_bsum[i >> 10];
        g_off[i] = f;
        g_cnt[i] = f;           // cursor
    } else if (i == N_NODES) {
        g_off[N_NODES] = N_EDGES;
    }
}

// ---------------------------------------------------------------------------
// Kernel E: permute edges into src-grouped order as (dst, w-bits) pairs
// ---------------------------------------------------------------------------
__global__ void __launch_bounds__(256) perm_kernel(
    const float* __restrict__ ew,
    const void* __restrict__ srcp,
    const void* __restrict__ dstp) {
    const int e = blockIdx.x * 256 + threadIdx.x;   // 1.6M exact
    const int idx64 = g_idx64;
    const int s = load_idx((const int*)srcp, e, idx64);
    const int d = load_idx((const int*)dstp, e, idx64);
    const float w = __ldg(ew + e);
    if ((unsigned)s < N_NODES) {
        const int pos = atomicAdd(&g_cnt[s], 1);
        g_pairs[pos] = make_int2(d, __float_as_int(w));
    }
}

// ---------------------------------------------------------------------------
// Kernel F: per-node aggregation + ReLU.  Half-warp (16 lanes) per node:
// lane hl covers cols [4hl, 4hl+3].  4-edge inner unroll: 4 independent
// pair-loads then 4 independent gathers in flight per iteration.
// ---------------------------------------------------------------------------
__global__ void __launch_bounds__(256) agg_kernel(float* __restrict__ out) {
    const int warp = threadIdx.x >> 5;
    const int lane = threadIdx.x & 31;
    const int half = lane >> 4;
    const int hl   = lane & 15;
    const int node = blockIdx.x * 16 + warp * 2 + half;   // 6250*16 = 100000

    const int b  = __ldg(&g_off[node]);
    const int e2 = __ldg(&g_off[node + 1]);

    float4 acc = make_float4(0.f, 0.f, 0.f, 0.f);

    int j = b;
    for (; j + 3 < e2; j += 4) {
        int2 c0 = __ldg(&g_pairs[j]);
        int2 c1 = __ldg(&g_pairs[j + 1]);
        int2 c2 = __ldg(&g_pairs[j + 2]);
        int2 c3 = __ldg(&g_pairs[j + 3]);
        const uint2 h0 = __ldg((const uint2*)(g_h16 + (size_t)c0.x * 32) + hl);
        const uint2 h1 = __ldg((const uint2*)(g_h16 + (size_t)c1.x * 32) + hl);
        const uint2 h2 = __ldg((const uint2*)(g_h16 + (size_t)c2.x * 32) + hl);
        const uint2 h3 = __ldg((const uint2*)(g_h16 + (size_t)c3.x * 32) + hl);
#pragma unroll
        for (int q = 0; q < 4; q++) {
            const uint2 hv = (q == 0) ? h0 : (q == 1) ? h1 : (q == 2) ? h2 : h3;
            const float wv = __int_as_float((q == 0) ? c0.y : (q == 1) ? c1.y
                                           : (q == 2) ? c2.y : c3.y);
            const float2 f0 = __half22float2(*(const __half2*)&hv.x);
            const float2 f1 = __half22float2(*(const __half2*)&hv.y);
            acc.x += wv * f0.x;
            acc.y += wv * f0.y;
            acc.z += wv * f1.x;
            acc.w += wv * f1.y;
        }
    }
    for (; j < e2; j++) {
        const int2 cur = __ldg(&g_pairs[j]);
        const uint2 hv = __ldg((const uint2*)(g_h16 + (size_t)cur.x * 32) + hl);
        const float wv = __int_as_float(cur.y);
        const float2 f0 = __half22float2(*(const __half2*)&hv.x);
        const float2 f1 = __half22float2(*(const __half2*)&hv.y);
        acc.x += wv * f0.x;
        acc.y += wv * f0.y;
        acc.z += wv * f1.x;
        acc.w += wv * f1.y;
    }

    float4 r;
    r.x = fmaxf(acc.x, 0.f);
    r.y = fmaxf(acc.y, 0.f);
    r.z = fmaxf(acc.z, 0.f);
    r.w = fmaxf(acc.w, 0.f);
    *(float4*)(out + (size_t)node * D_OUT + 4 * hl) = r;
}

// ---------------------------------------------------------------------------
extern "C" void kernel_launch(void* const* d_in, const int* in_sizes, int n_in,
                              void* d_out, int out_size) {
    const float* x   = (const float*)d_in[0];      // [100000, 128]
    const float* ew  = (const float*)d_in[1];      // [1600000]
    const float* W   = (const float*)d_in[2];      // [128, 64]
    const void*  src = d_in[3];                    // [1600000] int64/int32
    const void*  dst = d_in[4];                    // [1600000] int64/int32
    float* out = (float*)d_out;                    // [100000, 64]

    // Lazily-created side stream + fork/join events (host objects).
    static cudaStream_t s2 = nullptr;
    static cudaEvent_t ev_fork = nullptr, ev_join = nullptr;
    if (s2 == nullptr) {
        cudaStreamCreateWithFlags(&s2, cudaStreamNonBlocking);
        cudaEventCreateWithFlags(&ev_fork, cudaEventDisableTiming);
        cudaEventCreateWithFlags(&ev_join, cudaEventDisableTiming);
    }

    // ---- fork: CSR build runs on s2, concurrent with the GEMM.
    cudaEventRecord(ev_fork, 0);
    cudaStreamWaitEvent(s2, ev_fork, 0);

    // branch A (main stream): h = x @ W
    gemm_kernel<<<(N_NODES + 127) / 128, 128>>>(x, W);

    // branch B (s2): CSR build
    zero_probe_kernel<<<392, 256, 0, s2>>>(src);
    hist_kernel<<<N_EDGES / 256, 256, 0, s2>>>(src);
    scan1_kernel<<<98, 256, 0, s2>>>();
    scan2_kernel<<<1, 128, 0, s2>>>();
    scan3_kernel<<<392, 256, 0, s2>>>();
    perm_kernel<<<N_EDGES / 256, 256, 0, s2>>>(ew, src, dst);

    // ---- join, then aggregate (+ReLU) on the main stream
    cudaEventRecord(ev_join, s2);
    cudaStreamWaitEvent(0, ev_join, 0);
    agg_kernel<<<N_NODES / 16, 256>>>(out);
}